// round 15
// baseline (speedup 1.0000x reference)
#include <cuda_runtime.h>
#include <cuda_bf16.h>
#include <cstdint>
#include <math.h>

#define TOK       16384
#define HID       4096
#define HALF_DIM  2048
#define NEXP      64
#define TOPK      8
#define NSLICE    16          // HALF_DIM / TN

// ---------------- device scratch (no allocs allowed) ----------------
__device__ __align__(16) __nv_bfloat16 g_xhi[(size_t)TOK * HID];
__device__ __align__(16) __nv_bfloat16 g_xlo[(size_t)TOK * HID];
__device__ __align__(16) __nv_bfloat16 g_w1thi[(size_t)HALF_DIM * HID];
__device__ __align__(16) __nv_bfloat16 g_w1tlo[(size_t)HALF_DIM * HID];
__device__ __align__(16) float         g_part[(size_t)NSLICE * TOK * NEXP]; // 64 MB

// ---------------- PTX helpers (sm_80-era only; NO tcgen05 on compute_103) ----
__device__ __forceinline__ uint32_t smem_u32(const void* p) {
    uint32_t a;
    asm("{ .reg .u64 t; cvta.to.shared.u64 t, %1; cvt.u32.u64 %0, t; }" : "=r"(a) : "l"(p));
    return a;
}
__device__ __forceinline__ void cp16(uint32_t dst, const void* src) {
    asm volatile("cp.async.cg.shared.global [%0], [%1], 16;"
                 :: "r"(dst), "l"(__cvta_generic_to_global(src)) : "memory");
}
#define CP_COMMIT() asm volatile("cp.async.commit_group;" ::: "memory")
#define CP_WAIT0()  asm volatile("cp.async.wait_group 0;" ::: "memory")
#define CP_WAIT1()  asm volatile("cp.async.wait_group 1;" ::: "memory")

#define LDSM4(r, a) asm volatile( \
    "ldmatrix.sync.aligned.m8n8.x4.shared.b16 {%0,%1,%2,%3}, [%4];" \
    : "=r"((r)[0]), "=r"((r)[1]), "=r"((r)[2]), "=r"((r)[3]) : "r"(a))

#define MMA16816(d, a, b) asm volatile( \
    "mma.sync.aligned.m16n8k16.row.col.f32.bf16.bf16.f32 " \
    "{%0,%1,%2,%3}, {%4,%5,%6,%7}, {%8,%9}, {%0,%1,%2,%3};" \
    : "+f"((d)[0]), "+f"((d)[1]), "+f"((d)[2]), "+f"((d)[3]) \
    : "r"((a)[0]), "r"((a)[1]), "r"((a)[2]), "r"((a)[3]), "r"((b)[0]), "r"((b)[1]))

// ================= kernel 1: split x into bf16 hi/lo =================
__global__ __launch_bounds__(256) void split_x_kernel(const float* __restrict__ x) {
    size_t i = (size_t)blockIdx.x * 256 + threadIdx.x;   // one float4
    float4 v = reinterpret_cast<const float4*>(x)[i];
    float f[4] = {v.x, v.y, v.z, v.w};
    __nv_bfloat162 h01, h23, l01, l23;
    __nv_bfloat16 h, l;
    h = __float2bfloat16(f[0]); l = __float2bfloat16(f[0] - __bfloat162float(h)); h01.x = h; l01.x = l;
    h = __float2bfloat16(f[1]); l = __float2bfloat16(f[1] - __bfloat162float(h)); h01.y = h; l01.y = l;
    h = __float2bfloat16(f[2]); l = __float2bfloat16(f[2] - __bfloat162float(h)); h23.x = h; l23.x = l;
    h = __float2bfloat16(f[3]); l = __float2bfloat16(f[3] - __bfloat162float(h)); h23.y = h; l23.y = l;
    reinterpret_cast<__nv_bfloat162*>(g_xhi)[2 * i]     = h01;
    reinterpret_cast<__nv_bfloat162*>(g_xhi)[2 * i + 1] = h23;
    reinterpret_cast<__nv_bfloat162*>(g_xlo)[2 * i]     = l01;
    reinterpret_cast<__nv_bfloat162*>(g_xlo)[2 * i + 1] = l23;
}

// ============ kernel 2: split + transpose W1 -> W1^T hi/lo ============
__global__ void split_w1_kernel(const float* __restrict__ W1) {
    __shared__ float t[32][33];
    const int n0 = blockIdx.x * 32;   // over HALF_DIM
    const int k0 = blockIdx.y * 32;   // over HID
    const int tx = threadIdx.x, ty = threadIdx.y; // (32,8)
#pragma unroll
    for (int j = 0; j < 32; j += 8)
        t[ty + j][tx] = W1[(size_t)(k0 + ty + j) * HALF_DIM + n0 + tx];
    __syncthreads();
#pragma unroll
    for (int j = 0; j < 32; j += 8) {
        float v = t[tx][ty + j];
        __nv_bfloat16 h = __float2bfloat16(v);
        __nv_bfloat16 l = __float2bfloat16(v - __bfloat162float(h));
        size_t o = (size_t)(n0 + ty + j) * HID + k0 + tx;
        g_w1thi[o] = h;
        g_w1tlo[o] = l;
    }
}

// ====== kernel 3: GEMM1 mma.sync (3-term bf16) + GeLU + fused partial GEMM2 ======
#define TM 128
#define TN 128
#define KC 32
#define NCH (HID / KC)        // 128 chunks
#define RSTRIDE 80            // bytes per smem row (32 bf16 + 8 pad)
#define OFF_AHI 0
#define OFF_ALO 10240
#define OFF_BHI 20480
#define OFF_BLO 30720
#define STAGE_BYTES 40960
#define HS_STRIDE 129         // fp32 h-tile row stride (floats)
#define EPI_HS_BYTES (128 * HS_STRIDE * 4)          // 66048
#define GEMM1_SMEM (EPI_HS_BYTES + 128 * NEXP * 4)  // 98816 (>= 2*STAGE_BYTES)

__device__ __forceinline__ void g1_load(uint32_t stage, int c,
                                        size_t arow0, size_t brow0, int tid) {
    const int kb = c * KC;
#pragma unroll
    for (int j = 0; j < 8; ++j) {               // 2048 x 16B by 256 threads
        int i = tid + j * 256;
        int isB = i >> 10;
        int m   = (i >> 9) & 1;                 // hi / lo
        int idx = i & 511;
        int r = idx >> 2, u = idx & 3;
        const __nv_bfloat16* src = isB
            ? ((m ? g_w1tlo : g_w1thi) + (brow0 + (size_t)r) * HID + kb + u * 8)
            : ((m ? g_xlo   : g_xhi)   + (arow0 + (size_t)r) * HID + kb + u * 8);
        uint32_t dst = stage + (uint32_t)(isB ? OFF_BHI : OFF_AHI)
                     + (uint32_t)(m ? 10240 : 0)
                     + (uint32_t)(r * RSTRIDE + u * 16);
        cp16(dst, src);
    }
    CP_COMMIT();
}

__device__ __forceinline__ float gelu_exact(float f) {
    return 0.5f * f * (1.0f + erff(f * 0.70710678118654752f));
}

__global__ __launch_bounds__(256, 2) void gemm1_kernel(const float* __restrict__ b1,
                                                       const float* __restrict__ W2) {
    extern __shared__ __align__(128) char smem[];
    const uint32_t sb = smem_u32(smem);
    const int tid  = threadIdx.x;
    const int lane = tid & 31;
    const int w    = tid >> 5;          // 8 warps: 2(M) x 4(N)
    const int wm   = w >> 2;
    const int wn   = w & 3;
    const int bx   = blockIdx.x;
    const size_t arow0 = (size_t)(bx >> 4) * TM;   // N fast -> A L2 reuse
    const size_t brow0 = (size_t)(bx & 15) * TN;

    float acc[4][4][4];
#pragma unroll
    for (int mi = 0; mi < 4; ++mi)
#pragma unroll
        for (int ni = 0; ni < 4; ++ni)
#pragma unroll
            for (int r = 0; r < 4; ++r) acc[mi][ni][r] = 0.0f;

    // per-lane ldmatrix offsets
    const uint32_t aRow = (uint32_t)(wm * 64 + (lane & 15));
    const uint32_t aCol = (uint32_t)((lane >> 4) * 16);                 // bytes (k half)
    // B x4: two n8 tiles per ldmatrix: mats 0,1 -> ni even; mats 2,3 -> ni odd
    const uint32_t bRow = (uint32_t)(wn * 32 + ((lane >> 4) & 1) * 8 + (lane & 7));
    const uint32_t bCol = (uint32_t)(((lane >> 3) & 1) * 16);           // bytes (k half)

    g1_load(sb, 0, arow0, brow0, tid);

    for (int c = 0; c < NCH; ++c) {
        if (c + 1 < NCH) {
            g1_load(sb + (uint32_t)(((c + 1) & 1) * STAGE_BYTES), c + 1, arow0, brow0, tid);
            CP_WAIT1();
        } else {
            CP_WAIT0();
        }
        __syncthreads();
        const uint32_t st = sb + (uint32_t)((c & 1) * STAGE_BYTES);
#pragma unroll
        for (int ks = 0; ks < 2; ++ks) {
            // ---- load ALL fragments for this k-step up front ----
            uint32_t ah[16], al[16], bh[8], bl[8];
#pragma unroll
            for (int mi = 0; mi < 4; ++mi) {
                uint32_t aoff = (aRow + mi * 16) * RSTRIDE + aCol + ks * 32;
                LDSM4(ah + mi * 4, st + OFF_AHI + aoff);
            }
#pragma unroll
            for (int np = 0; np < 2; ++np) {
                uint32_t boff = (bRow + np * 16) * RSTRIDE + bCol + ks * 32;
                LDSM4(bh + np * 4, st + OFF_BHI + boff);
                LDSM4(bl + np * 4, st + OFF_BLO + boff);
            }
#pragma unroll
            for (int mi = 0; mi < 4; ++mi) {
                uint32_t aoff = (aRow + mi * 16) * RSTRIDE + aCol + ks * 32;
                LDSM4(al + mi * 4, st + OFF_ALO + aoff);
            }
            // ---- term-outer MMA passes: same-acc reuse distance = 16 MMAs ----
            // pass 1: hi*hi
#pragma unroll
            for (int mi = 0; mi < 4; ++mi)
#pragma unroll
                for (int ni = 0; ni < 4; ++ni)
                    MMA16816(acc[mi][ni], ah + mi * 4, bh + (ni >> 1) * 4 + (ni & 1) * 2);
            // pass 2: hi*lo (reuses ah)
#pragma unroll
            for (int mi = 0; mi < 4; ++mi)
#pragma unroll
                for (int ni = 0; ni < 4; ++ni)
                    MMA16816(acc[mi][ni], ah + mi * 4, bl + (ni >> 1) * 4 + (ni & 1) * 2);
            // pass 3: lo*hi (reuses bh)
#pragma unroll
            for (int mi = 0; mi < 4; ++mi)
#pragma unroll
                for (int ni = 0; ni < 4; ++ni)
                    MMA16816(acc[mi][ni], al + mi * 4, bh + (ni >> 1) * 4 + (ni & 1) * 2);
        }
        __syncthreads();
    }

    // ---------- fused epilogue: bias + GeLU -> smem h tile, then partial GEMM2 ----------
    float* hs  = reinterpret_cast<float*>(smem);                 // [128][129]
    float* w2s = reinterpret_cast<float*>(smem + EPI_HS_BYTES);  // [128][64]

    // stage W2 slice [128 k x 64 e]
#pragma unroll
    for (int j = 0; j < 8; ++j) {
        int i = tid + j * 256;
        int kk = i >> 4, e4 = (i & 15) * 4;
        *reinterpret_cast<float4*>(&w2s[kk * NEXP + e4]) =
            *reinterpret_cast<const float4*>(&W2[(brow0 + kk) * NEXP + e4]);
    }
    // store h tile (post-GeLU)
#pragma unroll
    for (int mi = 0; mi < 4; ++mi) {
#pragma unroll
        for (int ni = 0; ni < 4; ++ni) {
            const int col = wn * 32 + ni * 8 + (lane & 3) * 2;
            const float b0 = b1[brow0 + col];
            const float bI = b1[brow0 + col + 1];
            const int r0 = wm * 64 + mi * 16 + (lane >> 2);
            hs[r0 * HS_STRIDE + col]           = gelu_exact(acc[mi][ni][0] + b0);
            hs[r0 * HS_STRIDE + col + 1]       = gelu_exact(acc[mi][ni][1] + bI);
            hs[(r0 + 8) * HS_STRIDE + col]     = gelu_exact(acc[mi][ni][2] + b0);
            hs[(r0 + 8) * HS_STRIDE + col + 1] = gelu_exact(acc[mi][ni][3] + bI);
        }
    }
    __syncthreads();

    // partial logits: [128 tok x 64 exp] over this CTA's 128 h-cols
    {
        const int tok   = tid >> 1;
        const int ebase = (tid & 1) * 32;
        float a2[32];
#pragma unroll
        for (int e = 0; e < 32; ++e) a2[e] = 0.0f;
        const float* hrow = &hs[tok * HS_STRIDE];
        for (int k = 0; k < 128; ++k) {
            const float a = hrow[k];
            const float4* wr = reinterpret_cast<const float4*>(&w2s[k * NEXP + ebase]);
#pragma unroll
            for (int e4 = 0; e4 < 8; ++e4) {
                float4 wv = wr[e4];
                a2[e4 * 4 + 0] += a * wv.x;
                a2[e4 * 4 + 1] += a * wv.y;
                a2[e4 * 4 + 2] += a * wv.z;
                a2[e4 * 4 + 3] += a * wv.w;
            }
        }
        const int slice = bx & 15;
        float* dst = &g_part[(((size_t)slice * TOK) + arow0 + tok) * NEXP + ebase];
#pragma unroll
        for (int e4 = 0; e4 < 8; ++e4) {
            float4 v = {a2[e4 * 4], a2[e4 * 4 + 1], a2[e4 * 4 + 2], a2[e4 * 4 + 3]};
            *reinterpret_cast<float4*>(&dst[e4 * 4]) = v;
        }
    }
}

// ==== kernel 4: reduce partials + top-8 + softmax + scatter + mask ====
__global__ __launch_bounds__(256) void router_kernel(const float* __restrict__ am,
                                                     const float* __restrict__ b2,
                                                     float* __restrict__ out) {
    const int lid = threadIdx.x & 31;
    const int tok = blockIdx.x * 8 + (threadIdx.x >> 5);
    float v0 = b2[lid];
    float v1 = b2[32 + lid];
#pragma unroll
    for (int s = 0; s < NSLICE; ++s) {
        const float* p = &g_part[(((size_t)s * TOK) + tok) * NEXP];
        v0 += p[lid];
        v1 += p[32 + lid];
    }
    float a0 = v0, a1 = v1;
    float tv[TOPK]; int ti[TOPK];
#pragma unroll
    for (int it = 0; it < TOPK; ++it) {
        float cv; int ci;
        if (a0 >= a1) { cv = a0; ci = lid; } else { cv = a1; ci = lid + 32; }
#pragma unroll
        for (int off = 16; off > 0; off >>= 1) {
            float ov = __shfl_xor_sync(0xFFFFFFFFu, cv, off);
            int oi = __shfl_xor_sync(0xFFFFFFFFu, ci, off);
            if (ov > cv || (ov == cv && oi < ci)) { cv = ov; ci = oi; }
        }
        tv[it] = cv; ti[it] = ci;
        if (ci == lid) a0 = -__int_as_float(0x7F800000);
        if (ci == lid + 32) a1 = -__int_as_float(0x7F800000);
    }
    const float m = tv[0];
    float s = 0.0f, ex[TOPK];
#pragma unroll
    for (int it = 0; it < TOPK; ++it) { ex[it] = expf(tv[it] - m); s += ex[it]; }
    const float inv = 1.0f / s;
    float we0 = 0.0f, we1 = 0.0f;
#pragma unroll
    for (int it = 0; it < TOPK; ++it) {
        float wgt = ex[it] * inv;
        if (ti[it] == lid) we0 = wgt;
        if (ti[it] == lid + 32) we1 = wgt;
    }
    const float msk = am[tok];
    const size_t ob = (size_t)tok * NEXP;
    out[ob + lid] = we0 * msk;
    out[ob + 32 + lid] = we1 * msk;
    out[(size_t)TOK * NEXP + ob + lid] = v0 * msk;
    out[(size_t)TOK * NEXP + ob + 32 + lid] = v1 * msk;
}

// ============================== launch ==============================
extern "C" void kernel_launch(void* const* d_in, const int* in_sizes, int n_in,
                              void* d_out, int out_size) {
    const float *x = nullptr, *am = nullptr, *W1 = nullptr,
                *b1 = nullptr, *W2 = nullptr, *b2 = nullptr;
    for (int i = 0; i < n_in; ++i) {
        int s = in_sizes[i];
        if (s == 67108864) x = (const float*)d_in[i];        // 16384*4096
        else if (s == 16384) am = (const float*)d_in[i];     // 4*4096 mask
        else if (s == 8388608) W1 = (const float*)d_in[i];   // 4096*2048
        else if (s == 2048) b1 = (const float*)d_in[i];
        else if (s == 131072) W2 = (const float*)d_in[i];    // 2048*64
        else if (s == 64) b2 = (const float*)d_in[i];
    }
    float* out = (float*)d_out;

    cudaFuncSetAttribute(gemm1_kernel, cudaFuncAttributeMaxDynamicSharedMemorySize, GEMM1_SMEM);

    split_x_kernel<<<(TOK * HID / 4) / 256, 256>>>(x);
    split_w1_kernel<<<dim3(HALF_DIM / 32, HID / 32), dim3(32, 8)>>>(W1);
    gemm1_kernel<<<(TOK / TM) * (HALF_DIM / TN), 256, GEMM1_SMEM>>>(b1, W2);
    router_kernel<<<TOK / 8, 256>>>(am, b2, out);
}

// round 17
// speedup vs baseline: 1.5963x; 1.5963x over previous
#include <cuda_runtime.h>
#include <cuda_bf16.h>
#include <cstdint>
#include <math.h>

#define TOK       16384
#define HID       4096
#define HALF_DIM  2048
#define NEXP      64
#define TOPK      8
#define NSLICE    16          // HALF_DIM / TN

// ---------------- device scratch (no allocs allowed) ----------------
__device__ __align__(16) __nv_bfloat16 g_xhi[(size_t)TOK * HID];
__device__ __align__(16) __nv_bfloat16 g_xlo[(size_t)TOK * HID];
__device__ __align__(16) __nv_bfloat16 g_w1thi[(size_t)HALF_DIM * HID];
__device__ __align__(16) __nv_bfloat16 g_w1tlo[(size_t)HALF_DIM * HID];
__device__ __align__(16) float         g_part[(size_t)NSLICE * TOK * NEXP]; // 64 MB

// ---------------- PTX helpers (sm_80-era only; NO tcgen05 on compute_103) ----
__device__ __forceinline__ uint32_t smem_u32(const void* p) {
    uint32_t a;
    asm("{ .reg .u64 t; cvta.to.shared.u64 t, %1; cvt.u32.u64 %0, t; }" : "=r"(a) : "l"(p));
    return a;
}
__device__ __forceinline__ void cp16(uint32_t dst, const void* src) {
    asm volatile("cp.async.cg.shared.global [%0], [%1], 16;"
                 :: "r"(dst), "l"(__cvta_generic_to_global(src)) : "memory");
}
#define CP_COMMIT() asm volatile("cp.async.commit_group;" ::: "memory")
#define CP_WAIT0()  asm volatile("cp.async.wait_group 0;" ::: "memory")
#define CP_WAIT1()  asm volatile("cp.async.wait_group 1;" ::: "memory")

#define LDSM4(r, a) asm volatile( \
    "ldmatrix.sync.aligned.m8n8.x4.shared.b16 {%0,%1,%2,%3}, [%4];" \
    : "=r"((r)[0]), "=r"((r)[1]), "=r"((r)[2]), "=r"((r)[3]) : "r"(a))

#define MMA16816(d, a, b) asm volatile( \
    "mma.sync.aligned.m16n8k16.row.col.f32.bf16.bf16.f32 " \
    "{%0,%1,%2,%3}, {%4,%5,%6,%7}, {%8,%9}, {%0,%1,%2,%3};" \
    : "+f"((d)[0]), "+f"((d)[1]), "+f"((d)[2]), "+f"((d)[3]) \
    : "r"((a)[0]), "r"((a)[1]), "r"((a)[2]), "r"((a)[3]), "r"((b)[0]), "r"((b)[1]))

// ================= kernel 1: split x into bf16 hi/lo =================
__global__ __launch_bounds__(256) void split_x_kernel(const float* __restrict__ x) {
    size_t i = (size_t)blockIdx.x * 256 + threadIdx.x;   // one float4
    float4 v = reinterpret_cast<const float4*>(x)[i];
    float f[4] = {v.x, v.y, v.z, v.w};
    __nv_bfloat162 h01, h23, l01, l23;
    __nv_bfloat16 h, l;
    h = __float2bfloat16(f[0]); l = __float2bfloat16(f[0] - __bfloat162float(h)); h01.x = h; l01.x = l;
    h = __float2bfloat16(f[1]); l = __float2bfloat16(f[1] - __bfloat162float(h)); h01.y = h; l01.y = l;
    h = __float2bfloat16(f[2]); l = __float2bfloat16(f[2] - __bfloat162float(h)); h23.x = h; l23.x = l;
    h = __float2bfloat16(f[3]); l = __float2bfloat16(f[3] - __bfloat162float(h)); h23.y = h; l23.y = l;
    reinterpret_cast<__nv_bfloat162*>(g_xhi)[2 * i]     = h01;
    reinterpret_cast<__nv_bfloat162*>(g_xhi)[2 * i + 1] = h23;
    reinterpret_cast<__nv_bfloat162*>(g_xlo)[2 * i]     = l01;
    reinterpret_cast<__nv_bfloat162*>(g_xlo)[2 * i + 1] = l23;
}

// ============ kernel 2: split + transpose W1 -> W1^T hi/lo ============
__global__ void split_w1_kernel(const float* __restrict__ W1) {
    __shared__ float t[32][33];
    const int n0 = blockIdx.x * 32;   // over HALF_DIM
    const int k0 = blockIdx.y * 32;   // over HID
    const int tx = threadIdx.x, ty = threadIdx.y; // (32,8)
#pragma unroll
    for (int j = 0; j < 32; j += 8)
        t[ty + j][tx] = W1[(size_t)(k0 + ty + j) * HALF_DIM + n0 + tx];
    __syncthreads();
#pragma unroll
    for (int j = 0; j < 32; j += 8) {
        float v = t[tx][ty + j];
        __nv_bfloat16 h = __float2bfloat16(v);
        __nv_bfloat16 l = __float2bfloat16(v - __bfloat162float(h));
        size_t o = (size_t)(n0 + ty + j) * HID + k0 + tx;
        g_w1thi[o] = h;
        g_w1tlo[o] = l;
    }
}

// ====== kernel 3: GEMM1 mma.sync (3-term bf16) + GeLU + fused partial GEMM2 ======
#define TM 128
#define TN 128
#define KC 32
#define NCH (HID / KC)        // 128 chunks
#define RSTRIDE 80            // bytes per smem row (32 bf16 + 8 pad)
#define OFF_AHI 0
#define OFF_ALO 10240
#define OFF_BHI 20480
#define OFF_BLO 30720
#define STAGE_BYTES 40960
#define HS_STRIDE 129         // fp32 h-tile row stride (floats)
#define EPI_HS_BYTES (128 * HS_STRIDE * 4)          // 66048
#define GEMM1_SMEM (EPI_HS_BYTES + 128 * NEXP * 4)  // 98816 (>= 2*STAGE_BYTES)

__device__ __forceinline__ void g1_load(uint32_t stage, int c,
                                        size_t arow0, size_t brow0, int tid) {
    const int kb = c * KC;
#pragma unroll
    for (int j = 0; j < 8; ++j) {               // 2048 x 16B by 256 threads
        int i = tid + j * 256;
        int isB = i >> 10;
        int m   = (i >> 9) & 1;                 // hi / lo
        int idx = i & 511;
        int r = idx >> 2, u = idx & 3;
        const __nv_bfloat16* src = isB
            ? ((m ? g_w1tlo : g_w1thi) + (brow0 + (size_t)r) * HID + kb + u * 8)
            : ((m ? g_xlo   : g_xhi)   + (arow0 + (size_t)r) * HID + kb + u * 8);
        uint32_t dst = stage + (uint32_t)(isB ? OFF_BHI : OFF_AHI)
                     + (uint32_t)(m ? 10240 : 0)
                     + (uint32_t)(r * RSTRIDE + u * 16);
        cp16(dst, src);
    }
    CP_COMMIT();
}

__device__ __forceinline__ float gelu_exact(float f) {
    return 0.5f * f * (1.0f + erff(f * 0.70710678118654752f));
}

__global__ __launch_bounds__(256, 2) void gemm1_kernel(const float* __restrict__ b1,
                                                       const float* __restrict__ W2) {
    extern __shared__ __align__(128) char smem[];
    const uint32_t sb = smem_u32(smem);
    const int tid  = threadIdx.x;
    const int lane = tid & 31;
    const int w    = tid >> 5;          // 8 warps: 2(M) x 4(N)
    const int wm   = w >> 2;
    const int wn   = w & 3;
    const int bx   = blockIdx.x;
    const size_t arow0 = (size_t)(bx >> 4) * TM;   // N fast -> A L2 reuse
    const size_t brow0 = (size_t)(bx & 15) * TN;

    float acc[4][4][4];
#pragma unroll
    for (int mi = 0; mi < 4; ++mi)
#pragma unroll
        for (int ni = 0; ni < 4; ++ni)
#pragma unroll
            for (int r = 0; r < 4; ++r) acc[mi][ni][r] = 0.0f;

    // per-lane ldmatrix offsets
    const uint32_t aRow = (uint32_t)(wm * 64 + (lane & 15));
    const uint32_t aCol = (uint32_t)((lane >> 4) * 16);                 // bytes (k half)
    // B x4: two n8 tiles per ldmatrix: mats 0,1 -> ni even; mats 2,3 -> ni odd
    const uint32_t bRow = (uint32_t)(wn * 32 + ((lane >> 4) & 1) * 8 + (lane & 7));
    const uint32_t bCol = (uint32_t)(((lane >> 3) & 1) * 16);           // bytes (k half)

    g1_load(sb, 0, arow0, brow0, tid);

    for (int c = 0; c < NCH; ++c) {
        if (c + 1 < NCH) {
            g1_load(sb + (uint32_t)(((c + 1) & 1) * STAGE_BYTES), c + 1, arow0, brow0, tid);
            CP_WAIT1();
        } else {
            CP_WAIT0();
        }
        __syncthreads();
        const uint32_t st = sb + (uint32_t)((c & 1) * STAGE_BYTES);
#pragma unroll
        for (int ks = 0; ks < 2; ++ks) {
            uint32_t ah[16], al[16];
#pragma unroll
            for (int mi = 0; mi < 4; ++mi) {
                uint32_t aoff = (aRow + mi * 16) * RSTRIDE + aCol + ks * 32;
                LDSM4(ah + mi * 4, st + OFF_AHI + aoff);
                LDSM4(al + mi * 4, st + OFF_ALO + aoff);
            }
#pragma unroll
            for (int np = 0; np < 2; ++np) {     // ni pairs (0,1) and (2,3)
                uint32_t boff = (bRow + np * 16) * RSTRIDE + bCol + ks * 32;
                uint32_t bh[4], bl[4];
                LDSM4(bh, st + OFF_BHI + boff);
                LDSM4(bl, st + OFF_BLO + boff);
                // term-major within this np-pass: same-acc reuse distance = 8 MMAs,
                // register live set identical to the R14 (2437us) scheduler.
                // pass 1: hi*hi
#pragma unroll
                for (int mi = 0; mi < 4; ++mi)
#pragma unroll
                    for (int q = 0; q < 2; ++q)
                        MMA16816(acc[mi][np * 2 + q], ah + mi * 4, bh + q * 2);
                // pass 2: hi*lo
#pragma unroll
                for (int mi = 0; mi < 4; ++mi)
#pragma unroll
                    for (int q = 0; q < 2; ++q)
                        MMA16816(acc[mi][np * 2 + q], ah + mi * 4, bl + q * 2);
                // pass 3: lo*hi
#pragma unroll
                for (int mi = 0; mi < 4; ++mi)
#pragma unroll
                    for (int q = 0; q < 2; ++q)
                        MMA16816(acc[mi][np * 2 + q], al + mi * 4, bh + q * 2);
            }
        }
        __syncthreads();
    }

    // ---------- fused epilogue: bias + GeLU -> smem h tile, then partial GEMM2 ----------
    float* hs  = reinterpret_cast<float*>(smem);                 // [128][129]
    float* w2s = reinterpret_cast<float*>(smem + EPI_HS_BYTES);  // [128][64]

    // stage W2 slice [128 k x 64 e]
#pragma unroll
    for (int j = 0; j < 8; ++j) {
        int i = tid + j * 256;
        int kk = i >> 4, e4 = (i & 15) * 4;
        *reinterpret_cast<float4*>(&w2s[kk * NEXP + e4]) =
            *reinterpret_cast<const float4*>(&W2[(brow0 + kk) * NEXP + e4]);
    }
    // store h tile (post-GeLU)
#pragma unroll
    for (int mi = 0; mi < 4; ++mi) {
#pragma unroll
        for (int ni = 0; ni < 4; ++ni) {
            const int col = wn * 32 + ni * 8 + (lane & 3) * 2;
            const float b0 = b1[brow0 + col];
            const float bI = b1[brow0 + col + 1];
            const int r0 = wm * 64 + mi * 16 + (lane >> 2);
            hs[r0 * HS_STRIDE + col]           = gelu_exact(acc[mi][ni][0] + b0);
            hs[r0 * HS_STRIDE + col + 1]       = gelu_exact(acc[mi][ni][1] + bI);
            hs[(r0 + 8) * HS_STRIDE + col]     = gelu_exact(acc[mi][ni][2] + b0);
            hs[(r0 + 8) * HS_STRIDE + col + 1] = gelu_exact(acc[mi][ni][3] + bI);
        }
    }
    __syncthreads();

    // partial logits: [128 tok x 64 exp] over this CTA's 128 h-cols
    {
        const int tok   = tid >> 1;
        const int ebase = (tid & 1) * 32;
        float a2[32];
#pragma unroll
        for (int e = 0; e < 32; ++e) a2[e] = 0.0f;
        const float* hrow = &hs[tok * HS_STRIDE];
        for (int k = 0; k < 128; ++k) {
            const float a = hrow[k];
            const float4* wr = reinterpret_cast<const float4*>(&w2s[k * NEXP + ebase]);
#pragma unroll
            for (int e4 = 0; e4 < 8; ++e4) {
                float4 wv = wr[e4];
                a2[e4 * 4 + 0] += a * wv.x;
                a2[e4 * 4 + 1] += a * wv.y;
                a2[e4 * 4 + 2] += a * wv.z;
                a2[e4 * 4 + 3] += a * wv.w;
            }
        }
        const int slice = bx & 15;
        float* dst = &g_part[(((size_t)slice * TOK) + arow0 + tok) * NEXP + ebase];
#pragma unroll
        for (int e4 = 0; e4 < 8; ++e4) {
            float4 v = {a2[e4 * 4], a2[e4 * 4 + 1], a2[e4 * 4 + 2], a2[e4 * 4 + 3]};
            *reinterpret_cast<float4*>(&dst[e4 * 4]) = v;
        }
    }
}

// ==== kernel 4: reduce partials + top-8 + softmax + scatter + mask ====
__global__ __launch_bounds__(256) void router_kernel(const float* __restrict__ am,
                                                     const float* __restrict__ b2,
                                                     float* __restrict__ out) {
    const int lid = threadIdx.x & 31;
    const int tok = blockIdx.x * 8 + (threadIdx.x >> 5);
    float v0 = b2[lid];
    float v1 = b2[32 + lid];
#pragma unroll
    for (int s = 0; s < NSLICE; ++s) {
        const float* p = &g_part[(((size_t)s * TOK) + tok) * NEXP];
        v0 += p[lid];
        v1 += p[32 + lid];
    }
    float a0 = v0, a1 = v1;
    float tv[TOPK]; int ti[TOPK];
#pragma unroll
    for (int it = 0; it < TOPK; ++it) {
        float cv; int ci;
        if (a0 >= a1) { cv = a0; ci = lid; } else { cv = a1; ci = lid + 32; }
#pragma unroll
        for (int off = 16; off > 0; off >>= 1) {
            float ov = __shfl_xor_sync(0xFFFFFFFFu, cv, off);
            int oi = __shfl_xor_sync(0xFFFFFFFFu, ci, off);
            if (ov > cv || (ov == cv && oi < ci)) { cv = ov; ci = oi; }
        }
        tv[it] = cv; ti[it] = ci;
        if (ci == lid) a0 = -__int_as_float(0x7F800000);
        if (ci == lid + 32) a1 = -__int_as_float(0x7F800000);
    }
    const float m = tv[0];
    float s = 0.0f, ex[TOPK];
#pragma unroll
    for (int it = 0; it < TOPK; ++it) { ex[it] = expf(tv[it] - m); s += ex[it]; }
    const float inv = 1.0f / s;
    float we0 = 0.0f, we1 = 0.0f;
#pragma unroll
    for (int it = 0; it < TOPK; ++it) {
        float wgt = ex[it] * inv;
        if (ti[it] == lid) we0 = wgt;
        if (ti[it] == lid + 32) we1 = wgt;
    }
    const float msk = am[tok];
    const size_t ob = (size_t)tok * NEXP;
    out[ob + lid] = we0 * msk;
    out[ob + 32 + lid] = we1 * msk;
    out[(size_t)TOK * NEXP + ob + lid] = v0 * msk;
    out[(size_t)TOK * NEXP + ob + 32 + lid] = v1 * msk;
}

// ============================== launch ==============================
extern "C" void kernel_launch(void* const* d_in, const int* in_sizes, int n_in,
                              void* d_out, int out_size) {
    const float *x = nullptr, *am = nullptr, *W1 = nullptr,
                *b1 = nullptr, *W2 = nullptr, *b2 = nullptr;
    for (int i = 0; i < n_in; ++i) {
        int s = in_sizes[i];
        if (s == 67108864) x = (const float*)d_in[i];        // 16384*4096
        else if (s == 16384) am = (const float*)d_in[i];     // 4*4096 mask
        else if (s == 8388608) W1 = (const float*)d_in[i];   // 4096*2048
        else if (s == 2048) b1 = (const float*)d_in[i];
        else if (s == 131072) W2 = (const float*)d_in[i];    // 2048*64
        else if (s == 64) b2 = (const float*)d_in[i];
    }
    float* out = (float*)d_out;

    cudaFuncSetAttribute(gemm1_kernel, cudaFuncAttributeMaxDynamicSharedMemorySize, GEMM1_SMEM);

    split_x_kernel<<<(TOK * HID / 4) / 256, 256>>>(x);
    split_w1_kernel<<<dim3(HALF_DIM / 32, HID / 32), dim3(32, 8)>>>(W1);
    gemm1_kernel<<<(TOK / TM) * (HALF_DIM / TN), 256, GEMM1_SMEM>>>(b1, W2);
    router_kernel<<<TOK / 8, 256>>>(am, b2, out);
}